// round 4
// baseline (speedup 1.0000x reference)
#include <cuda_runtime.h>
#include <math.h>

#define NN 192
#define TT 20
#define DH 64
#define DE 32
#define DR 32

// Persistent / scratch state (no allocations allowed)
__device__ float g_h[NN*DH], g_c[NN*DH];
__device__ float g_h1[NN*DH], g_c1[NN*DH], g_og[NN*DH];
__device__ float g_h2[NN*DH], g_c2[NN*DH];
__device__ float g_A[NN*DH], g_B[NN*DH], g_a[NN], g_b[NN];
__device__ float g_acc[4];
__device__ float g_v[3];

__global__ void init_kernel(float* out) {
    int tid = blockIdx.x * blockDim.x + threadIdx.x;
    if (tid < NN*DH) { g_h[tid] = 0.f; g_c[tid] = 0.f; }
    if (tid < 4) g_acc[tid] = 0.f;
    if (tid < 3) g_v[tid] = 0.f;
    if (tid < NN*2) out[(TT-1)*NN*2 + tid] = 0.f;  // outputs[T-1] = 0
}

// LSTM cell: one block per node i, 64 threads (one per hidden unit)
__global__ void lstm_kernel(int t, const float* __restrict__ norm,
                            const float* __restrict__ w_in, const float* __restrict__ b_in,
                            const float* __restrict__ w_ih, const float* __restrict__ w_hh,
                            const float* __restrict__ b_ih, const float* __restrict__ b_hh) {
    int i = blockIdx.x;
    int k = threadIdx.x; // 0..63
    __shared__ float sx[DE];
    __shared__ float sh[DH];
    if (k < DE) {
        float n0 = norm[(t*NN + i)*2 + 0];
        float n1 = norm[(t*NN + i)*2 + 1];
        float v = n0 * w_in[k*2 + 0] + n1 * w_in[k*2 + 1] + b_in[k];
        sx[k] = v > 0.f ? v : 0.f;
    }
    sh[k] = g_h[i*DH + k];
    __syncthreads();

    float acc[4];
#pragma unroll
    for (int q = 0; q < 4; q++) {
        int r = q*DH + k;
        float a = b_ih[r] + b_hh[r];
        const float* wi = w_ih + r*DE;
        const float* wh = w_hh + r*DH;
#pragma unroll
        for (int e = 0; e < DE; e++) a += sx[e] * wi[e];
#pragma unroll
        for (int e = 0; e < DH; e++) a += sh[e] * wh[e];
        acc[q] = a;
    }
    float ig = 1.f / (1.f + __expf(-acc[0]));
    float fg = 1.f / (1.f + __expf(-acc[1]));
    float gg = tanhf(acc[2]);
    float og = 1.f / (1.f + __expf(-acc[3]));
    float c1 = fg * g_c[i*DH + k] + ig * gg;
    float h1 = og * tanhf(c1);
    g_c1[i*DH + k] = c1;
    g_h1[i*DH + k] = h1;
    g_og[i*DH + k] = og;
}

// Per-node precompute for gcn: A[i][h], B[i][h], a[i], b[i].
// stage==1 also finalizes the per-step scalar ratios (from gcn0 accumulators).
__global__ void pre_kernel(int stage, const float* __restrict__ w_gate,
                           const float* __restrict__ w_ar) {
    int i = blockIdx.x, h = threadIdx.x;
    if (stage == 1 && i == 0 && h == 0) {
        const float eps = 1e-6f;
        g_v[0] += g_acc[0] / (g_acc[1] * (float)DH + eps);
        g_v[1] += g_acc[2] / (g_acc[3] + eps);
        g_v[2] += g_acc[1] / (float)NN;
        g_acc[0] = g_acc[1] = g_acc[2] = g_acc[3] = 0.f;
    }
    const float* hcur = stage ? g_h2 : g_h1;
    const float* wg = w_gate + stage * DH * 160;
    const float* war = w_ar + stage * 160;

    __shared__ float sh[DH];
    sh[h] = hcur[i*DH + h];
    __syncthreads();

    float A = 0.f, B = 0.f;
    const float* wA = wg + h*160 + 32;
    const float* wB = wg + h*160 + 96;
#pragma unroll
    for (int kk = 0; kk < DH; kk++) { A += sh[kk] * wA[kk]; B += sh[kk] * wB[kk]; }
    g_A[i*DH + h] = A;
    g_B[i*DH + h] = B;
    if (h == 0) { float a = 0.f; for (int kk = 0; kk < DH; kk++) a += sh[kk] * war[32 + kk]; g_a[i] = a; }
    if (h == 1) { float b = 0.f; for (int kk = 0; kk < DH; kk++) b += sh[kk] * war[96 + kk]; g_b[i] = b; }
}

// GCN row kernel: one block per row i, 256 threads.
// stage 0: h1/c1 -> h2/c2, accumulates scalar stats.
// stage 1: h2/c2 -> masked writeback to g_h/g_c + output row.
__global__ void row_kernel(int t, int stage,
                           const float* __restrict__ abs_, const int* __restrict__ seq,
                           const int* __restrict__ nei,
                           const float* __restrict__ w_rel, const float* __restrict__ b_rel,
                           const float* __restrict__ w_gate, const float* __restrict__ b_gate,
                           const float* __restrict__ w_ar, const float* __restrict__ b_ar,
                           const float* __restrict__ w_nei,
                           const float* __restrict__ w_out, const float* __restrict__ b_out,
                           float* __restrict__ out) {
    int i = blockIdx.x;
    int tid = threadIdx.x;
    int lane = tid & 31, warp = tid >> 5;
    int p = stage;
    const float* hcur = stage ? g_h2 : g_h1;
    const float* cin  = stage ? g_c2 : g_c1;
    float* hout = stage ? g_h : g_h2;
    float* cout = stage ? g_c : g_c2;
    const float* wrel = w_rel + p*DR*2;
    const float* brel = b_rel + p*DR;
    const float* wg   = w_gate + p*DH*160;
    const float* bg   = b_gate + p*DH;
    const float* war  = w_ar + p*160;
    const float  bar  = b_ar[p];
    const float* wnei = w_nei + p*DH*DH;

    __shared__ float s_r[NN*33];        // padded r[j][k]
    __shared__ float s_wgT[DR*DH];      // transposed Wg[:, :32]
    __shared__ float s_pos[NN];
    __shared__ int   s_active[NN];
    __shared__ int   s_cnt;
    __shared__ float s_Ai[DH];
    __shared__ float s_msg[8*DH];
    __shared__ float s_msgf[DH];
    __shared__ float s_red[256];
    __shared__ float s_hn[DH];

    for (int idx = tid; idx < DR*DH; idx += 256) {
        int k = idx >> 6, h = idx & 63;
        s_wgT[k*DH + h] = wg[h*160 + k];
    }
    if (tid < DH) s_Ai[tid] = g_A[i*DH + tid];
    if (tid == 0) s_cnt = 0;
    int mi = seq[t*NN + i] > 0;
    float ax = abs_[(t*NN + i)*2 + 0];
    float ay = abs_[(t*NN + i)*2 + 1];
    float a_i = g_a[i];
    __syncthreads();

    float my_neif = 0.f, my_score = -1e30f;
    if (tid < NN) {
        int j = tid;
        int mj = seq[t*NN + j] > 0;
        int nv = nei[(size_t)t*NN*NN + (size_t)i*NN + j];
        float neif = (nv > 0 && mi && mj) ? 1.f : 0.f;
        float cx = ax - abs_[(t*NN + j)*2 + 0];
        float cy = ay - abs_[(t*NN + j)*2 + 1];
        float sc = 0.f;
#pragma unroll
        for (int k = 0; k < DR; k++) {
            float rv = cx * wrel[k*2 + 0] + cy * wrel[k*2 + 1] + brel[k];
            rv = rv > 0.f ? rv : 0.f;
            s_r[j*33 + k] = rv;
            sc += rv * war[k];
        }
        sc += a_i + g_b[j] + bar;
        my_score = (neif > 0.f) ? sc : -1e9f;
        my_neif = neif;
        if (neif > 0.f) { int q = atomicAdd(&s_cnt, 1); s_active[q] = j; }
    }
    __syncthreads();

    // block-wide softmax over j
    s_red[tid] = (tid < NN) ? my_score : -1e30f;
    __syncthreads();
    for (int s = 128; s > 0; s >>= 1) { if (tid < s) s_red[tid] = fmaxf(s_red[tid], s_red[tid + s]); __syncthreads(); }
    float mx = s_red[0];
    __syncthreads();
    float e = (tid < NN) ? __expf(my_score - mx) : 0.f;
    s_red[tid] = e;
    __syncthreads();
    for (int s = 128; s > 0; s >>= 1) { if (tid < s) s_red[tid] += s_red[tid + s]; __syncthreads(); }
    float inv = 1.f / s_red[0];
    __syncthreads();
    float posv = (tid < NN) ? e * inv * my_neif : 0.f;
    if (tid < NN) s_pos[tid] = posv;

    // scalar row-stats (cheap; always computed, only atomically committed for stage 0)
    s_red[tid] = (tid < NN) ? my_neif : 0.f;
    __syncthreads();
    for (int s = 128; s > 0; s >>= 1) { if (tid < s) s_red[tid] += s_red[tid + s]; __syncthreads(); }
    float neiRow = s_red[0];
    __syncthreads();
    s_red[tid] = posv;
    __syncthreads();
    for (int s = 128; s > 0; s >>= 1) { if (tid < s) s_red[tid] = fmaxf(s_red[tid], s_red[tid + s]); __syncthreads(); }
    float maxposRow = s_red[0];
    __syncthreads();

    // Phase 3: gate + message over active neighbors only (8 warps strided)
    float msg0 = 0.f, msg1 = 0.f, v1p = 0.f;
    int cnt = s_cnt;
    for (int a = warp; a < cnt; a += 8) {
        int j = s_active[a];
        float pj = s_pos[j];
        float hj0 = hcur[j*DH + lane];
        float hj1 = hcur[j*DH + 32 + lane];
        float B0 = g_B[j*DH + lane];
        float B1 = g_B[j*DH + 32 + lane];
        float acc0 = s_Ai[lane] + B0 + bg[lane];
        float acc1 = s_Ai[32 + lane] + B1 + bg[32 + lane];
        const float* rj = &s_r[j*33];
#pragma unroll
        for (int k = 0; k < DR; k++) {
            float rv = rj[k];
            acc0 += rv * s_wgT[k*DH + lane];
            acc1 += rv * s_wgT[k*DH + 32 + lane];
        }
        float g0 = 1.f / (1.f + __expf(-acc0));
        float g1 = 1.f / (1.f + __expf(-acc1));
        msg0 += pj * g0 * hj0;
        msg1 += pj * g1 * hj1;
        v1p += g0 + g1;
    }
    s_msg[warp*DH + lane] = msg0;
    s_msg[warp*DH + 32 + lane] = msg1;
    s_red[tid] = v1p;
    __syncthreads();
    for (int s = 128; s > 0; s >>= 1) { if (tid < s) s_red[tid] += s_red[tid + s]; __syncthreads(); }
    float gateSum = s_red[0];
    __syncthreads();

    // Phase 4: reduce msg, update c/h
    if (tid < DH) {
        float m = 0.f;
#pragma unroll
        for (int w = 0; w < 8; w++) m += s_msg[w*DH + tid];
        s_msgf[tid] = m;
    }
    __syncthreads();
    if (tid < DH) {
        float cn = cin[i*DH + tid];
        const float* wn = wnei + tid*DH;
#pragma unroll
        for (int k = 0; k < DH; k++) cn += s_msgf[k] * wn[k];
        float hn = g_og[i*DH + tid] * tanhf(cn);
        if (stage == 1) {
            s_hn[tid] = hn;
            if (mi) { hout[i*DH + tid] = hn; cout[i*DH + tid] = cn; }
        } else {
            hout[i*DH + tid] = hn;
            cout[i*DH + tid] = cn;
        }
    }
    if (stage == 1) {
        __syncthreads();
        if (tid < 2) {
            float o = b_out[tid];
            for (int k = 0; k < DH; k++) o += s_hn[k] * w_out[tid*DH + k];
            out[(t*NN + i)*2 + tid] = mi ? o : 0.f;
        }
    } else {
        if (tid == 0) {
            atomicAdd(&g_acc[0], gateSum);
            atomicAdd(&g_acc[1], neiRow);
            atomicAdd(&g_acc[2], maxposRow);
            atomicAdd(&g_acc[3], neiRow > 0.f ? 1.f : 0.f);
        }
    }
}

__global__ void final_kernel(float* out) {
    int tid = blockIdx.x * blockDim.x + threadIdx.x;
    const int OFF = TT*NN*2;
    if (tid < NN*DH) {
        out[OFF + tid] = g_h[tid];
        out[OFF + NN*DH + tid] = g_c[tid];
    }
    if (tid < 3) out[OFF + 2*NN*DH + tid] = g_v[tid] / (float)TT;
}

extern "C" void kernel_launch(void* const* d_in, const int* in_sizes, int n_in,
                              void* d_out, int out_size) {
    const float* abs_   = (const float*)d_in[0];
    const float* norm   = (const float*)d_in[1];
    // d_in[2] shift_value: unused by reference
    const float* w_in   = (const float*)d_in[3];
    const float* b_in   = (const float*)d_in[4];
    const float* w_ih   = (const float*)d_in[5];
    const float* w_hh   = (const float*)d_in[6];
    const float* b_ih   = (const float*)d_in[7];
    const float* b_hh   = (const float*)d_in[8];
    const float* w_rel  = (const float*)d_in[9];
    const float* b_rel  = (const float*)d_in[10];
    const float* w_gate = (const float*)d_in[11];
    const float* b_gate = (const float*)d_in[12];
    const float* w_ar   = (const float*)d_in[13];
    const float* b_ar   = (const float*)d_in[14];
    const float* w_nei  = (const float*)d_in[15];
    const float* w_out  = (const float*)d_in[16];
    const float* b_out  = (const float*)d_in[17];
    const int*   seq    = (const int*)d_in[18];
    const int*   nei    = (const int*)d_in[19];
    // d_in[20] nei_num: unused by reference
    float* out = (float*)d_out;

    init_kernel<<<48, 256>>>(out);
    for (int t = 0; t < TT - 1; t++) {
        lstm_kernel<<<NN, 64>>>(t, norm, w_in, b_in, w_ih, w_hh, b_ih, b_hh);
        pre_kernel<<<NN, 64>>>(0, w_gate, w_ar);
        row_kernel<<<NN, 256>>>(t, 0, abs_, seq, nei, w_rel, b_rel, w_gate, b_gate,
                                w_ar, b_ar, w_nei, w_out, b_out, out);
        pre_kernel<<<NN, 64>>>(1, w_gate, w_ar);
        row_kernel<<<NN, 256>>>(t, 1, abs_, seq, nei, w_rel, b_rel, w_gate, b_gate,
                                w_ar, b_ar, w_nei, w_out, b_out, out);
    }
    final_kernel<<<48, 256>>>(out);
}

// round 5
// speedup vs baseline: 1.2113x; 1.2113x over previous
#include <cuda_runtime.h>
#include <math.h>

#define NN 192
#define TT 20
#define DH 64
#define DE 32
#define DR 32
#define NB NN
#define NTH 256

// Persistent state (no allocations allowed)
__device__ float g_h[NN*DH], g_c[NN*DH];
__device__ float g_h1[NN*DH], g_c1[NN*DH], g_og[NN*DH];
__device__ float g_h2[NN*DH], g_c2[NN*DH];
__device__ float g_A0[NN*DH], g_B0[NN*DH], g_a0[NN], g_b0[NN];
__device__ float g_A1[NN*DH], g_B1[NN*DH], g_a1[NN], g_b1[NN];
__device__ float g_acc[4];
__device__ float g_v[3];
__device__ unsigned g_bar[2];   // [0]=count  [1]=epoch  (memset to 0 each launch)

// Grid-wide barrier: monotonic epoch, release/acquire at gpu scope.
__device__ __forceinline__ void gbar(unsigned& sense) {
    __syncthreads();
    if (threadIdx.x == 0) {
        unsigned want = sense + 1u;
        __threadfence();
        unsigned a = atomicAdd(&g_bar[0], 1u);
        if (a == NB - 1u) {
            g_bar[0] = 0u;
            asm volatile("st.release.gpu.u32 [%0], %1;" :: "l"(&g_bar[1]), "r"(want) : "memory");
        } else {
            unsigned v;
            for (;;) {
                asm volatile("ld.acquire.gpu.u32 %0, [%1];" : "=r"(v) : "l"(&g_bar[1]) : "memory");
                if (v >= want) break;
                __nanosleep(64);
            }
        }
    }
    __syncthreads();
    sense += 1u;
}

// One GCN pass for row i. STAGE 0: h1/c1 -> h2/c2 (+stats atomics, +pre1).
// STAGE 1: h2/c2 -> masked writeback to g_h/g_c, + output row.
template <int STAGE>
__device__ __forceinline__ void row_phase(
    int t, int i, int tid, int lane, int warp, int mi,
    const float* __restrict__ hcur, const float* __restrict__ cin,
    float* __restrict__ hout, float* __restrict__ cout,
    const float* __restrict__ gA, const float* __restrict__ gB,
    const float* __restrict__ ga, const float* __restrict__ gb_,
    const float* __restrict__ abs_, const int* __restrict__ seq,
    const int* __restrict__ nei,
    const float* __restrict__ bg, float barv,
    const float* __restrict__ wnei,
    const float* __restrict__ w_gate, const float* __restrict__ w_ar,
    const float* __restrict__ w_out, const float* __restrict__ b_out,
    float* __restrict__ out,
    const float* s_wg_stage, const float4* s_cst,
    float* s_r, float* s_pos, int* s_active, int* s_cnt,
    float* s_msg, float* s_msgf, float* s_hn,
    float* s_redA, float* s_redB, float* s_bc)
{
    float ax = abs_[(t*NN + i)*2 + 0];
    float ay = abs_[(t*NN + i)*2 + 1];
    float a_i = ga[i];
    if (tid == 0) *s_cnt = 0;
    __syncthreads();

    float my_neif = 0.f, my_score = -1e30f;
    if (tid < NN) {
        int j = tid;
        int mj = seq[t*NN + j] > 0;
        int nv = nei[(size_t)t*NN*NN + (size_t)i*NN + j];
        float neif = (nv > 0 && mi && mj) ? 1.f : 0.f;
        float cx = ax - abs_[(t*NN + j)*2 + 0];
        float cy = ay - abs_[(t*NN + j)*2 + 1];
        float sc = 0.f;
#pragma unroll
        for (int k = 0; k < DR; k++) {
            float4 c4 = s_cst[k];   // {wrel_x, wrel_y, brel, war}
            float rv = fmaxf(cx*c4.x + cy*c4.y + c4.z, 0.f);
            s_r[k*NN + j] = rv;
            sc += rv * c4.w;
        }
        sc += a_i + gb_[j] + barv;
        my_score = (neif > 0.f) ? sc : -1e9f;
        my_neif = neif;
        if (neif > 0.f) { int q = atomicAdd(s_cnt, 1); s_active[q] = j; }
    }

    // pass1: max(score), sum(neif)
    float m = my_score, sn = my_neif;
#pragma unroll
    for (int o = 16; o; o >>= 1) {
        m = fmaxf(m, __shfl_xor_sync(0xffffffffu, m, o));
        sn += __shfl_xor_sync(0xffffffffu, sn, o);
    }
    if (lane == 0) { s_redA[warp] = m; s_redB[warp] = sn; }
    __syncthreads();
    if (tid == 0) {
        float mm = s_redA[0], ss = s_redB[0];
#pragma unroll
        for (int w = 1; w < 8; w++) { mm = fmaxf(mm, s_redA[w]); ss += s_redB[w]; }
        s_bc[0] = mm; s_bc[1] = ss;
    }
    __syncthreads();
    float mx = s_bc[0];
    float neiRow = s_bc[1];
    float e  = (tid < NN) ? __expf(my_score - mx) : 0.f;
    float en = e * my_neif;
    __syncthreads();

    // pass2: sum(e), max(e*neif)
    float se = e, mn = en;
#pragma unroll
    for (int o = 16; o; o >>= 1) {
        se += __shfl_xor_sync(0xffffffffu, se, o);
        mn = fmaxf(mn, __shfl_xor_sync(0xffffffffu, mn, o));
    }
    if (lane == 0) { s_redA[warp] = se; s_redB[warp] = mn; }
    __syncthreads();
    if (tid == 0) {
        float ss = s_redA[0], mm = s_redB[0];
#pragma unroll
        for (int w = 1; w < 8; w++) { ss += s_redA[w]; mm = fmaxf(mm, s_redB[w]); }
        s_bc[0] = ss; s_bc[1] = mm;
    }
    __syncthreads();
    float inv = 1.f / s_bc[0];
    float maxposRow = s_bc[1] * inv;
    float posv = e * inv * my_neif;
    if (tid < NN) s_pos[tid] = posv;
    __syncthreads();

    // gate + message over active neighbors (8 warps strided)
    float Ai0 = gA[i*DH + lane] + bg[lane];
    float Ai1 = gA[i*DH + 32 + lane] + bg[32 + lane];
    float msg0 = 0.f, msg1 = 0.f, v1p = 0.f;
    int cnt = *s_cnt;
    for (int a = warp; a < cnt; a += 8) {
        int j = s_active[a];
        float pj  = s_pos[j];
        float acc0 = Ai0 + gB[j*DH + lane];
        float acc1 = Ai1 + gB[j*DH + 32 + lane];
        float hj0 = hcur[j*DH + lane];
        float hj1 = hcur[j*DH + 32 + lane];
        const float* rj = s_r + j;
#pragma unroll
        for (int k = 0; k < DR; k++) {
            float rv = rj[k*NN];
            acc0 += rv * s_wg_stage[k*DH + lane];
            acc1 += rv * s_wg_stage[k*DH + 32 + lane];
        }
        float g0 = 1.f/(1.f+__expf(-acc0));
        float g1 = 1.f/(1.f+__expf(-acc1));
        msg0 += pj*g0*hj0;
        msg1 += pj*g1*hj1;
        v1p  += g0 + g1;
    }
    s_msg[warp*DH + lane]      = msg0;
    s_msg[warp*DH + 32 + lane] = msg1;
#pragma unroll
    for (int o = 16; o; o >>= 1) v1p += __shfl_xor_sync(0xffffffffu, v1p, o);
    if (lane == 0) s_redA[warp] = v1p;
    __syncthreads();

    // reduce msg, update c/h
    if (tid < DH) {
        float mg = 0.f;
#pragma unroll
        for (int w = 0; w < 8; w++) mg += s_msg[w*DH + tid];
        s_msgf[tid] = mg;
    }
    __syncthreads();
    if (tid < DH) {
        float cn = cin[i*DH + tid];
        const float* wn = wnei + tid*DH;
#pragma unroll
        for (int k = 0; k < DH; k++) cn += s_msgf[k]*wn[k];
        float hn = g_og[i*DH + tid] * tanhf(cn);
        s_hn[tid] = hn;
        if (STAGE == 1) {
            if (mi) { hout[i*DH + tid] = hn; cout[i*DH + tid] = cn; }
        } else {
            hout[i*DH + tid] = hn; cout[i*DH + tid] = cn;
        }
    }
    __syncthreads();

    if (STAGE == 0) {
        // stats
        if (tid == 0) {
            float gateSum = 0.f;
#pragma unroll
            for (int w = 0; w < 8; w++) gateSum += s_redA[w];
            atomicAdd(&g_acc[0], gateSum);
            atomicAdd(&g_acc[1], neiRow);
            atomicAdd(&g_acc[2], maxposRow);
            atomicAdd(&g_acc[3], neiRow > 0.f ? 1.f : 0.f);
        }
        // pre1 from h2[i] (own row only)
        if (tid < 128) {
            int h = tid & 63;
            const float* w = w_gate + DH*160 + h*160 + ((tid < 64) ? 32 : 96);
            float acc = 0.f;
#pragma unroll
            for (int k = 0; k < DH; k++) acc += s_hn[k]*w[k];
            if (tid < 64) g_A1[i*DH + h] = acc; else g_B1[i*DH + h] = acc;
        } else if (tid < 130) {
            const float* w = w_ar + 160 + ((tid == 128) ? 32 : 96);
            float acc = 0.f;
            for (int k = 0; k < DH; k++) acc += s_hn[k]*w[k];
            if (tid == 128) g_a1[i] = acc; else g_b1[i] = acc;
        }
    } else {
        if (tid < 2) {
            float o = b_out[tid];
            for (int k = 0; k < DH; k++) o += s_hn[k]*w_out[tid*DH + k];
            out[(t*NN + i)*2 + tid] = mi ? o : 0.f;
        }
    }
}

__global__ void __launch_bounds__(NTH, 2)
fused_kernel(const float* __restrict__ abs_, const float* __restrict__ norm,
             const float* __restrict__ w_in, const float* __restrict__ b_in,
             const float* __restrict__ w_ih, const float* __restrict__ w_hh,
             const float* __restrict__ b_ih, const float* __restrict__ b_hh,
             const float* __restrict__ w_rel, const float* __restrict__ b_rel,
             const float* __restrict__ w_gate, const float* __restrict__ b_gate,
             const float* __restrict__ w_ar, const float* __restrict__ b_ar,
             const float* __restrict__ w_nei, const float* __restrict__ w_out,
             const float* __restrict__ b_out,
             const int* __restrict__ seq, const int* __restrict__ nei,
             float* __restrict__ out)
{
    __shared__ float s_wg[2*DR*DH];                 // 16KB: Wg[:, :32]^T both stages
    __shared__ __align__(16) float s_cst[2*DR*4];   // 1KB: {wrel_x,wrel_y,brel,war} both
    __shared__ float s_r[DR*NN];                    // 24KB
    __shared__ float s_pos[NN];
    __shared__ int   s_active[NN];
    __shared__ float s_msg[8*DH];
    __shared__ float s_gates[NTH];
    __shared__ float s_xh[96];
    __shared__ float s_hn[DH];
    __shared__ float s_msgf[DH];
    __shared__ float s_redA[8], s_redB[8];
    __shared__ float s_bc[2];
    __shared__ int   s_cnt;

    const int i = blockIdx.x;
    const int tid = threadIdx.x;
    const int lane = tid & 31, warp = tid >> 5;
    unsigned sense = 0;

    // one-time preloads (persist across all steps)
    for (int idx = tid; idx < 2*DR*DH; idx += NTH) {
        int p = idx >> 11, r = idx & 2047;
        int k = r >> 6, h = r & 63;
        s_wg[idx] = w_gate[p*DH*160 + h*160 + k];
    }
    for (int idx = tid; idx < 2*DR; idx += NTH) {
        int p = idx >> 5, k = idx & 31;
        s_cst[(p*DR + k)*4 + 0] = w_rel[p*DR*2 + k*2 + 0];
        s_cst[(p*DR + k)*4 + 1] = w_rel[p*DR*2 + k*2 + 1];
        s_cst[(p*DR + k)*4 + 2] = b_rel[p*DR + k];
        s_cst[(p*DR + k)*4 + 3] = w_ar[p*160 + k];
    }
    if (tid < DH) { g_h[i*DH + tid] = 0.f; g_c[i*DH + tid] = 0.f; }
    if (tid < 2)  out[((TT-1)*NN + i)*2 + tid] = 0.f;
    if (i == 0 && tid < 4) g_acc[tid] = 0.f;
    if (i == 0 && tid < 3) g_v[tid] = 0.f;

    for (int t = 0; t < TT-1; t++) {
        //======== Phase A: LSTM cell for node i + pre0 (own-row only) ========
        int mi = seq[t*NN + i] > 0;
        if (tid < DE) {
            float n0 = norm[(t*NN + i)*2 + 0];
            float n1 = norm[(t*NN + i)*2 + 1];
            float v = n0*w_in[tid*2 + 0] + n1*w_in[tid*2 + 1] + b_in[tid];
            s_xh[tid] = fmaxf(v, 0.f);
        }
        if (tid < DH) s_xh[32 + tid] = g_h[i*DH + tid];
        __syncthreads();
        {
            float a = b_ih[tid] + b_hh[tid];
            const float* wi = w_ih + tid*DE;
            const float* wh = w_hh + tid*DH;
#pragma unroll
            for (int e2 = 0; e2 < DE; e2++) a += s_xh[e2]*wi[e2];
#pragma unroll
            for (int e2 = 0; e2 < DH; e2++) a += s_xh[32 + e2]*wh[e2];
            s_gates[tid] = a;
        }
        __syncthreads();
        if (tid < DH) {
            float ig = 1.f/(1.f+__expf(-s_gates[tid]));
            float fg = 1.f/(1.f+__expf(-s_gates[DH + tid]));
            float gg = tanhf(s_gates[2*DH + tid]);
            float og = 1.f/(1.f+__expf(-s_gates[3*DH + tid]));
            float c1 = fg*g_c[i*DH + tid] + ig*gg;
            float h1 = og*tanhf(c1);
            g_c1[i*DH + tid] = c1;
            g_h1[i*DH + tid] = h1;
            g_og[i*DH + tid] = og;
            s_hn[tid] = h1;
        }
        __syncthreads();
        if (tid < 128) {
            int h = tid & 63;
            const float* w = w_gate + h*160 + ((tid < 64) ? 32 : 96);
            float acc = 0.f;
#pragma unroll
            for (int k = 0; k < DH; k++) acc += s_hn[k]*w[k];
            if (tid < 64) g_A0[i*DH + h] = acc; else g_B0[i*DH + h] = acc;
        } else if (tid < 130) {
            const float* w = w_ar + ((tid == 128) ? 32 : 96);
            float acc = 0.f;
            for (int k = 0; k < DH; k++) acc += s_hn[k]*w[k];
            if (tid == 128) g_a0[i] = acc; else g_b0[i] = acc;
        }
        gbar(sense);

        //======== Phase B: GCN pass 0 (+pre1, +stats) ========
        row_phase<0>(t, i, tid, lane, warp, mi,
                     g_h1, g_c1, g_h2, g_c2,
                     g_A0, g_B0, g_a0, g_b0,
                     abs_, seq, nei,
                     b_gate, b_ar[0], w_nei,
                     w_gate, w_ar, w_out, b_out, out,
                     s_wg, (const float4*)s_cst,
                     s_r, s_pos, s_active, &s_cnt,
                     s_msg, s_msgf, s_hn, s_redA, s_redB, s_bc);
        gbar(sense);

        //======== Phase C: finalize stats + GCN pass 1 + outputs ========
        if (i == 0 && tid == 0) {
            const float eps = 1e-6f;
            g_v[0] += g_acc[0] / (g_acc[1]*(float)DH + eps);
            g_v[1] += g_acc[2] / (g_acc[3] + eps);
            g_v[2] += g_acc[1] / (float)NN;
            g_acc[0] = g_acc[1] = g_acc[2] = g_acc[3] = 0.f;
        }
        row_phase<1>(t, i, tid, lane, warp, mi,
                     g_h2, g_c2, g_h, g_c,
                     g_A1, g_B1, g_a1, g_b1,
                     abs_, seq, nei,
                     b_gate + DH, b_ar[1], w_nei + DH*DH,
                     w_gate, w_ar, w_out, b_out, out,
                     s_wg + DR*DH, (const float4*)(s_cst + DR*4),
                     s_r, s_pos, s_active, &s_cnt,
                     s_msg, s_msgf, s_hn, s_redA, s_redB, s_bc);
        // No grid barrier needed: phase A(t+1) touches only own-row state that
        // phase C of other blocks never reads; the barrier after A(t+1) orders
        // everything cross-block before phase B(t+1).
    }

    // final h, c, scalars (all own-block data)
    const int OFF = TT*NN*2;
    if (tid < DH) {
        out[OFF + i*DH + tid]         = g_h[i*DH + tid];
        out[OFF + NN*DH + i*DH + tid] = g_c[i*DH + tid];
    }
    if (i == 0 && tid < 3) out[OFF + 2*NN*DH + tid] = g_v[tid] / (float)TT;
}

extern "C" void kernel_launch(void* const* d_in, const int* in_sizes, int n_in,
                              void* d_out, int out_size) {
    const float* abs_   = (const float*)d_in[0];
    const float* norm   = (const float*)d_in[1];
    const float* w_in   = (const float*)d_in[3];
    const float* b_in   = (const float*)d_in[4];
    const float* w_ih   = (const float*)d_in[5];
    const float* w_hh   = (const float*)d_in[6];
    const float* b_ih   = (const float*)d_in[7];
    const float* b_hh   = (const float*)d_in[8];
    const float* w_rel  = (const float*)d_in[9];
    const float* b_rel  = (const float*)d_in[10];
    const float* w_gate = (const float*)d_in[11];
    const float* b_gate = (const float*)d_in[12];
    const float* w_ar   = (const float*)d_in[13];
    const float* b_ar   = (const float*)d_in[14];
    const float* w_nei  = (const float*)d_in[15];
    const float* w_out  = (const float*)d_in[16];
    const float* b_out  = (const float*)d_in[17];
    const int*   seq    = (const int*)d_in[18];
    const int*   nei    = (const int*)d_in[19];
    float* out = (float*)d_out;

    // Reset barrier state deterministically each launch (capturable memset node).
    void* barptr = nullptr;
    cudaGetSymbolAddress(&barptr, g_bar);
    cudaMemsetAsync(barptr, 0, 2*sizeof(unsigned), 0);

    fused_kernel<<<NB, NTH>>>(abs_, norm, w_in, b_in, w_ih, w_hh, b_ih, b_hh,
                              w_rel, b_rel, w_gate, b_gate, w_ar, b_ar,
                              w_nei, w_out, b_out, seq, nei, out);
}

// round 6
// speedup vs baseline: 1.6947x; 1.3991x over previous
#include <cuda_runtime.h>
#include <math.h>

#define NN 192
#define TT 20
#define DH 64
#define DE 32
#define DR 32
#define NB 48
#define NTH 512
#define RPB 4
#define TPR 128

// ---- device scratch (no allocations allowed) ----
__device__ float g_h1[NN*DH], g_h2[NN*DH];         // post-LSTM / post-gcn0 h (cross-block)
__device__ float g_B0[NN*DH], g_B1[NN*DH];         // pre B-parts (cross-block)
__device__ float g_b0v[NN], g_b1v[NN];             // pre b scalars (cross-block)
__device__ float g_acc[4], g_v[3];
__device__ unsigned g_bar[2];                      // memset to 0 each launch
// transposed weights (built once at kernel start)
__device__ float g_wihT[DE*256];                   // [e][r]
__device__ float g_whhT[DH*256];                   // [e][r]
__device__ float g_wABT[2*2*64*64];                // [p][part][k][h]
__device__ float g_wneiT[2*64*64];                 // [p][k][h]

__device__ __forceinline__ void gbar(unsigned& sense) {
    __syncthreads();
    if (threadIdx.x == 0) {
        unsigned want = sense + 1u;
        __threadfence();
        unsigned a = atomicAdd(&g_bar[0], 1u);
        if (a == NB - 1u) {
            g_bar[0] = 0u;
            asm volatile("st.release.gpu.u32 [%0], %1;" :: "l"(&g_bar[1]), "r"(want) : "memory");
        } else {
            unsigned v;
            for (;;) {
                asm volatile("ld.acquire.gpu.u32 %0, [%1];" : "=r"(v) : "l"(&g_bar[1]) : "memory");
                if (v >= want) break;
                __nanosleep(32);
            }
        }
    }
    __syncthreads();
    sense += 1u;
}

__device__ __forceinline__ float wsum(float v) {
#pragma unroll
    for (int o = 16; o; o >>= 1) v += __shfl_xor_sync(0xffffffffu, v, o);
    return v;
}
__device__ __forceinline__ float wmax(float v) {
#pragma unroll
    for (int o = 16; o; o >>= 1) v = fmaxf(v, __shfl_xor_sync(0xffffffffu, v, o));
    return v;
}

__global__ void __launch_bounds__(NTH, 1)
fused_kernel(const float* __restrict__ abs_, const float* __restrict__ norm,
             const float* __restrict__ w_in, const float* __restrict__ b_in,
             const float* __restrict__ w_ih, const float* __restrict__ w_hh,
             const float* __restrict__ b_ih, const float* __restrict__ b_hh,
             const float* __restrict__ w_rel, const float* __restrict__ b_rel,
             const float* __restrict__ w_gate, const float* __restrict__ b_gate,
             const float* __restrict__ w_ar, const float* __restrict__ b_ar,
             const float* __restrict__ w_nei, const float* __restrict__ w_out,
             const float* __restrict__ b_out,
             const int* __restrict__ seq, const int* __restrict__ nei,
             float* __restrict__ out)
{
    // ---- shared state (persistent across the whole scan) ----
    __shared__ float s_wgT[2*DR*DH];          // [p][k][h] Wg[:, :32]^T
    __shared__ __align__(16) float4 s_cst4[2*DR];  // {wrel_x,wrel_y,brel,war_k}
    __shared__ float s_war[2*2*DH];           // [p][part][k] w_ar slices
    __shared__ float s_bcomb[256];            // b_ih + b_hh
    __shared__ float s_bg[2*DH];              // b_gate
    __shared__ float s_bar2[2];               // b_ar
    __shared__ float s_abs[2*NN];             // abs[t] prefetch
    __shared__ unsigned char s_seqb[NN];      // seq[t] > 0
    __shared__ unsigned char s_neib[RPB][NN]; // nei[t,i,:] > 0
    __shared__ float s_gates[RPB][256];       // LSTM gates / msgf scratch
    __shared__ float s_xh[RPB][96];
    __shared__ float s_pos[RPB][NN];
    __shared__ unsigned char s_actb[RPB][NN];
    __shared__ float s_msgM[RPB][4][DH];
    __shared__ float s_hn[RPB][DH];
    __shared__ float s_A[RPB][DH];
    __shared__ float s_a[RPB];
    __shared__ float s_rr[RPB][16];
    __shared__ float s_v1[RPB][4];
    __shared__ float s_h[RPB][DH], s_c[RPB][DH];
    __shared__ float s_og[RPB][DH], s_ctmp[RPB][DH];
    __shared__ int   s_cnt[RPB];

    const int tid  = threadIdx.x;
    const int g    = tid >> 7;            // row group 0..3
    const int ltid = tid & 127;           // 0..127 within group
    const int lane = tid & 31;
    const int w4   = (tid >> 5) & 3;      // warp within group
    const int i    = blockIdx.x * RPB + g;
    const int gtid = blockIdx.x * NTH + tid;
    unsigned sense = 0;

    // ---- one-time smem constant loads ----
    for (int idx = tid; idx < 2*DR*DH; idx += NTH) {
        int p = idx >> 11, r = idx & 2047, k = r >> 6, h = r & 63;
        s_wgT[idx] = w_gate[p*DH*160 + h*160 + k];
    }
    for (int idx = tid; idx < 2*DR; idx += NTH) {
        int p = idx >> 5, k = idx & 31;
        s_cst4[idx] = make_float4(w_rel[p*DR*2 + k*2 + 0], w_rel[p*DR*2 + k*2 + 1],
                                  b_rel[p*DR + k],          w_ar[p*160 + k]);
    }
    for (int idx = tid; idx < 2*2*DH; idx += NTH) {
        int p = idx >> 7, part = (idx >> 6) & 1, k = idx & 63;
        s_war[idx] = w_ar[p*160 + 32 + part*64 + k];
    }
    if (tid < 256) s_bcomb[tid] = b_ih[tid] + b_hh[tid];
    if (tid < 2*DH) s_bg[tid] = b_gate[tid];
    if (tid < 2) s_bar2[tid] = b_ar[tid];
    if (ltid < DH) { s_h[g][ltid] = 0.f; s_c[g][ltid] = 0.f; }

    // ---- one-time global transposes + zero init ----
    for (int idx = gtid; idx < DE*256; idx += NB*NTH) {
        int e = idx >> 8, r = idx & 255;
        g_wihT[idx] = w_ih[r*DE + e];
    }
    for (int idx = gtid; idx < DH*256; idx += NB*NTH) {
        int e = idx >> 8, r = idx & 255;
        g_whhT[idx] = w_hh[r*DH + e];
    }
    for (int idx = gtid; idx < 2*2*64*64; idx += NB*NTH) {
        int h = idx & 63, k = (idx >> 6) & 63, part = (idx >> 12) & 1, p = idx >> 13;
        g_wABT[idx] = w_gate[p*DH*160 + h*160 + 32 + part*64 + k];
    }
    for (int idx = gtid; idx < 2*64*64; idx += NB*NTH) {
        int h = idx & 63, k = (idx >> 6) & 63, p = idx >> 12;
        g_wneiT[idx] = w_nei[p*DH*DH + h*DH + k];
    }
    if (gtid < NN*2) out[(TT-1)*NN*2 + gtid] = 0.f;
    if (blockIdx.x == 0 && tid < 4) g_acc[tid] = 0.f;
    if (blockIdx.x == 0 && tid < 3) g_v[tid] = 0.f;
    gbar(sense);

    for (int t = 0; t < TT-1; t++) {
        //================ Phase A: prefetch + LSTM + pre0 ================
        if (tid < 2*NN) s_abs[tid] = abs_[t*NN*2 + tid];
        if (tid < NN)   s_seqb[tid] = (unsigned char)(seq[t*NN + tid] > 0);
        for (int jj = ltid; jj < NN; jj += TPR)
            s_neib[g][jj] = (unsigned char)(nei[(size_t)t*NN*NN + (size_t)i*NN + jj] > 0);
        if (ltid < DE) {
            float n0 = norm[(t*NN + i)*2 + 0];
            float n1 = norm[(t*NN + i)*2 + 1];
            s_xh[g][ltid] = fmaxf(n0*w_in[ltid*2 + 0] + n1*w_in[ltid*2 + 1] + b_in[ltid], 0.f);
        }
        if (ltid < DH) s_xh[g][32 + ltid] = s_h[g][ltid];
        __syncthreads();
        {
            int r0 = ltid, r1 = ltid + 128;
            float a0 = s_bcomb[r0], a1 = s_bcomb[r1];
#pragma unroll
            for (int e = 0; e < DE; e++) {
                float x = s_xh[g][e];
                a0 += x * g_wihT[e*256 + r0];
                a1 += x * g_wihT[e*256 + r1];
            }
#pragma unroll
            for (int e = 0; e < DH; e++) {
                float x = s_xh[g][32 + e];
                a0 += x * g_whhT[e*256 + r0];
                a1 += x * g_whhT[e*256 + r1];
            }
            s_gates[g][r0] = a0;
            s_gates[g][r1] = a1;
        }
        __syncthreads();
        if (ltid < DH) {
            int h = ltid;
            float ig = 1.f/(1.f+__expf(-s_gates[g][h]));
            float fg = 1.f/(1.f+__expf(-s_gates[g][64 + h]));
            float gg = tanhf(s_gates[g][128 + h]);
            float og = 1.f/(1.f+__expf(-s_gates[g][192 + h]));
            float c1 = fg*s_c[g][h] + ig*gg;
            float h1 = og*tanhf(c1);
            s_ctmp[g][h] = c1;
            s_og[g][h] = og;
            s_hn[g][h] = h1;
            g_h1[i*DH + h] = h1;
        }
        __syncthreads();
        {   // pre0: A-part -> smem, B-part -> global
            int h = ltid & 63, part = ltid >> 6;
            const float* wp = g_wABT + (part*64)*64;   // stage 0
            float acc = 0.f;
#pragma unroll
            for (int k = 0; k < DH; k++) acc += s_hn[g][k]*wp[k*64 + h];
            if (part == 0) s_A[g][h] = acc; else g_B0[i*DH + h] = acc;
        }
        if (w4 == 0) {
            float pa = s_hn[g][lane]*s_war[lane] + s_hn[g][32+lane]*s_war[32+lane];
            pa = wsum(pa);
            if (lane == 0) s_a[g] = pa;
        } else if (w4 == 1) {
            float pb = s_hn[g][lane]*s_war[64+lane] + s_hn[g][32+lane]*s_war[96+lane];
            pb = wsum(pb);
            if (lane == 0) g_b0v[i] = pb;
        }
        gbar(sense);

        //================ Phases B (stage0) and C (stage1) ================
#pragma unroll 1
        for (int STAGE = 0; STAGE < 2; STAGE++) {
            if (STAGE == 1 && blockIdx.x == 0 && tid == 0) {
                const float eps = 1e-6f;
                g_v[0] += g_acc[0] / (g_acc[1]*(float)DH + eps);
                g_v[1] += g_acc[2] / (g_acc[3] + eps);
                g_v[2] += g_acc[1] / (float)NN;
                g_acc[0] = g_acc[1] = g_acc[2] = g_acc[3] = 0.f;
            }
            const float* hcur = STAGE ? g_h2 : g_h1;
            const float* gB   = STAGE ? g_B1 : g_B0;
            const float* gbv  = STAGE ? g_b1v : g_b0v;
            const float barv  = s_bar2[STAGE];
            const float aI    = s_a[g];
            const int   mi    = s_seqb[i];
            const float ax = s_abs[2*i], ay = s_abs[2*i+1];
            const float4* cst = s_cst4 + STAGE*DR;

            if (ltid == 0) s_cnt[g] = 0;
            // entry: scores for j1 = ltid, j2 = 128+ltid (ltid<64)
            const bool has2 = ltid < 64;
            int j1 = ltid, j2 = 128 + ltid;
            float nf1, nf2 = 0.f, sc1, sc2 = -1e30f;
            float cx1, cy1, cx2 = 0.f, cy2 = 0.f;
            {
                nf1 = (s_neib[g][j1] && mi && s_seqb[j1]) ? 1.f : 0.f;
                cx1 = ax - s_abs[2*j1]; cy1 = ay - s_abs[2*j1+1];
                float sc = 0.f;
#pragma unroll
                for (int k = 0; k < DR; k++) {
                    float4 c4 = cst[k];
                    float rv = fmaxf(fmaf(cx1, c4.x, fmaf(cy1, c4.y, c4.z)), 0.f);
                    sc += rv * c4.w;
                }
                sc += aI + __ldcg(&gbv[j1]) + barv;
                sc1 = (nf1 > 0.f) ? sc : -1e9f;
            }
            if (has2) {
                nf2 = (s_neib[g][j2] && mi && s_seqb[j2]) ? 1.f : 0.f;
                cx2 = ax - s_abs[2*j2]; cy2 = ay - s_abs[2*j2+1];
                float sc = 0.f;
#pragma unroll
                for (int k = 0; k < DR; k++) {
                    float4 c4 = cst[k];
                    float rv = fmaxf(fmaf(cx2, c4.x, fmaf(cy2, c4.y, c4.z)), 0.f);
                    sc += rv * c4.w;
                }
                sc += aI + __ldcg(&gbv[j2]) + barv;
                sc2 = (nf2 > 0.f) ? sc : -1e9f;
            }
            // reduce 1: max score, sum neif
            {
                float m = wmax(fmaxf(sc1, sc2));
                float sn = wsum(nf1 + nf2);
                if (lane == 0) { s_rr[g][w4] = m; s_rr[g][4 + w4] = sn; }
            }
            __syncthreads();
            float mm = fmaxf(fmaxf(s_rr[g][0], s_rr[g][1]), fmaxf(s_rr[g][2], s_rr[g][3]));
            float neiRow = s_rr[g][4] + s_rr[g][5] + s_rr[g][6] + s_rr[g][7];
            float e1 = __expf(sc1 - mm);
            float e2 = has2 ? __expf(sc2 - mm) : 0.f;
            // reduce 2: sum e, max e*neif
            {
                float se = wsum(e1 + e2);
                float mn = wmax(fmaxf(e1*nf1, e2*nf2));
                if (lane == 0) { s_rr[g][8 + w4] = se; s_rr[g][12 + w4] = mn; }
            }
            __syncthreads();
            float inv = 1.f / (s_rr[g][8] + s_rr[g][9] + s_rr[g][10] + s_rr[g][11]);
            float maxposRow = fmaxf(fmaxf(s_rr[g][12], s_rr[g][13]),
                                    fmaxf(s_rr[g][14], s_rr[g][15])) * inv;
            s_pos[g][j1] = e1 * inv * nf1;
            if (has2) s_pos[g][j2] = e2 * inv * nf2;
            // active-list compaction (ballot)
            {
                unsigned b1 = __ballot_sync(0xffffffffu, nf1 > 0.f);
                int base = 0;
                if (lane == 0) base = atomicAdd(&s_cnt[g], __popc(b1));
                base = __shfl_sync(0xffffffffu, base, 0);
                if (nf1 > 0.f) s_actb[g][base + __popc(b1 & ((1u << lane) - 1u))] = (unsigned char)j1;
                if (w4 < 2) {
                    unsigned b2 = __ballot_sync(0xffffffffu, nf2 > 0.f);
                    int base2 = 0;
                    if (lane == 0) base2 = atomicAdd(&s_cnt[g], __popc(b2));
                    base2 = __shfl_sync(0xffffffffu, base2, 0);
                    if (nf2 > 0.f) s_actb[g][base2 + __popc(b2 & ((1u << lane) - 1u))] = (unsigned char)j2;
                }
            }
            __syncthreads();
            // gate + message loop over active neighbors
            const float Ai0 = s_A[g][lane]      + s_bg[STAGE*DH + lane];
            const float Ai1 = s_A[g][32 + lane] + s_bg[STAGE*DH + 32 + lane];
            const float* wgS = s_wgT + STAGE*DR*DH;
            float msg0 = 0.f, msg1 = 0.f, v1p = 0.f;
            int cnt = s_cnt[g];
            for (int a = w4; a < cnt; a += 4) {
                int j = s_actb[g][a];
                float pj = s_pos[g][j];
                float cx = ax - s_abs[2*j], cy = ay - s_abs[2*j+1];
                float acc0 = Ai0 + __ldcg(&gB[j*DH + lane]);
                float acc1 = Ai1 + __ldcg(&gB[j*DH + 32 + lane]);
                float hj0 = __ldcg(&hcur[j*DH + lane]);
                float hj1 = __ldcg(&hcur[j*DH + 32 + lane]);
#pragma unroll
                for (int k = 0; k < DR; k++) {
                    float4 c4 = cst[k];
                    float rv = fmaxf(fmaf(cx, c4.x, fmaf(cy, c4.y, c4.z)), 0.f);
                    acc0 += rv * wgS[k*DH + lane];
                    acc1 += rv * wgS[k*DH + 32 + lane];
                }
                float g0 = 1.f/(1.f+__expf(-acc0));
                float g1 = 1.f/(1.f+__expf(-acc1));
                msg0 += pj*g0*hj0;
                msg1 += pj*g1*hj1;
                v1p  += g0 + g1;
            }
            s_msgM[g][w4][lane]      = msg0;
            s_msgM[g][w4][32 + lane] = msg1;
            v1p = wsum(v1p);
            if (lane == 0) s_v1[g][w4] = v1p;
            __syncthreads();
            if (ltid < DH)
                s_gates[g][ltid] = s_msgM[g][0][ltid] + s_msgM[g][1][ltid]
                                 + s_msgM[g][2][ltid] + s_msgM[g][3][ltid];
            __syncthreads();
            if (ltid < DH) {
                int h = ltid;
                float cn = s_ctmp[g][h];
                const float* wn = g_wneiT + STAGE*DH*DH;
#pragma unroll
                for (int k = 0; k < DH; k++) cn += s_gates[g][k]*wn[k*DH + h];
                float hn = s_og[g][h]*tanhf(cn);
                s_hn[g][h] = hn;
                if (STAGE == 0) {
                    s_ctmp[g][h] = cn;
                    g_h2[i*DH + h] = hn;
                } else if (mi) {
                    s_h[g][h] = hn; s_c[g][h] = cn;
                }
            }
            __syncthreads();
            if (STAGE == 0) {
                {   // pre1
                    int h = ltid & 63, part = ltid >> 6;
                    const float* wp = g_wABT + ((2 + part)*64)*64;  // stage 1
                    float acc = 0.f;
#pragma unroll
                    for (int k = 0; k < DH; k++) acc += s_hn[g][k]*wp[k*64 + h];
                    if (part == 0) s_A[g][h] = acc; else g_B1[i*DH + h] = acc;
                }
                if (w4 == 0) {
                    float pa = s_hn[g][lane]*s_war[128+lane] + s_hn[g][32+lane]*s_war[160+lane];
                    pa = wsum(pa);
                    if (lane == 0) s_a[g] = pa;
                } else if (w4 == 1) {
                    float pb = s_hn[g][lane]*s_war[192+lane] + s_hn[g][32+lane]*s_war[224+lane];
                    pb = wsum(pb);
                    if (lane == 0) g_b1v[i] = pb;
                }
                if (ltid == 0) {
                    float gateSum = s_v1[g][0] + s_v1[g][1] + s_v1[g][2] + s_v1[g][3];
                    atomicAdd(&g_acc[0], gateSum);
                    atomicAdd(&g_acc[1], neiRow);
                    atomicAdd(&g_acc[2], maxposRow);
                    atomicAdd(&g_acc[3], neiRow > 0.f ? 1.f : 0.f);
                }
                gbar(sense);
            } else {
                if (ltid < 2) {
                    float o = b_out[ltid];
#pragma unroll
                    for (int k = 0; k < DH; k++) o += s_hn[g][k]*w_out[ltid*DH + k];
                    out[(t*NN + i)*2 + ltid] = mi ? o : 0.f;
                }
            }
        }
        // no barrier between C and next A (A touches only own-row state)
    }

    // final writeback (own rows, own smem)
    const int OFF = TT*NN*2;
    if (ltid < DH) {
        out[OFF + i*DH + ltid]         = s_h[g][ltid];
        out[OFF + NN*DH + i*DH + ltid] = s_c[g][ltid];
    }
    if (blockIdx.x == 0 && tid < 3) out[OFF + 2*NN*DH + tid] = g_v[tid] / (float)TT;
}

extern "C" void kernel_launch(void* const* d_in, const int* in_sizes, int n_in,
                              void* d_out, int out_size) {
    const float* abs_   = (const float*)d_in[0];
    const float* norm   = (const float*)d_in[1];
    const float* w_in   = (const float*)d_in[3];
    const float* b_in   = (const float*)d_in[4];
    const float* w_ih   = (const float*)d_in[5];
    const float* w_hh   = (const float*)d_in[6];
    const float* b_ih   = (const float*)d_in[7];
    const float* b_hh   = (const float*)d_in[8];
    const float* w_rel  = (const float*)d_in[9];
    const float* b_rel  = (const float*)d_in[10];
    const float* w_gate = (const float*)d_in[11];
    const float* b_gate = (const float*)d_in[12];
    const float* w_ar   = (const float*)d_in[13];
    const float* b_ar   = (const float*)d_in[14];
    const float* w_nei  = (const float*)d_in[15];
    const float* w_out  = (const float*)d_in[16];
    const float* b_out  = (const float*)d_in[17];
    const int*   seq    = (const int*)d_in[18];
    const int*   nei    = (const int*)d_in[19];
    float* out = (float*)d_out;

    void* barptr = nullptr;
    cudaGetSymbolAddress(&barptr, g_bar);
    cudaMemsetAsync(barptr, 0, 2*sizeof(unsigned), 0);

    fused_kernel<<<NB, NTH>>>(abs_, norm, w_in, b_in, w_ih, w_hh, b_ih, b_hh,
                              w_rel, b_rel, w_gate, b_gate, w_ar, b_ar,
                              w_nei, w_out, b_out, seq, nei, out);
}